// round 7
// baseline (speedup 1.0000x reference)
#include <cuda_runtime.h>
#include <cuda_fp16.h>
#include <math.h>
#include <stdint.h>

#define BATCH 8
#define SEQ   2048
#define EMB   1024
#define HD    64
#define NROWS (BATCH*SEQ)   // 16384

__device__ __half g_q[NROWS*HD];
__device__ __half g_k[NROWS*HD];
__device__ __half g_v[NROWS*HD];
__device__ __half g_wt[3][HD*EMB];   // [o][n][k] transposed fp16
// flash-decoding partials
__device__ float g_po[2][NROWS*HD];
__device__ float g_pm[2][NROWS];
__device__ float g_pl[2][NROWS];

// ---------------------------------------------------------------------------
__device__ __forceinline__ void mma_f16(float d[4],
                                        uint32_t a0, uint32_t a1, uint32_t a2, uint32_t a3,
                                        uint32_t b0, uint32_t b1) {
    asm volatile(
        "mma.sync.aligned.m16n8k16.row.col.f32.f16.f16.f32 "
        "{%0,%1,%2,%3},{%4,%5,%6,%7},{%8,%9},{%0,%1,%2,%3};\n"
        : "+f"(d[0]), "+f"(d[1]), "+f"(d[2]), "+f"(d[3])
        : "r"(a0), "r"(a1), "r"(a2), "r"(a3), "r"(b0), "r"(b1));
}
__device__ __forceinline__ uint32_t pack_h2(float lo, float hi) {
    __half2 h = __floats2half2_rn(lo, hi);
    return *(uint32_t*)&h;
}
__device__ __forceinline__ void ldmatrix_x4_t(uint32_t r[4], uint32_t saddr) {
    asm volatile("ldmatrix.sync.aligned.m8n8.x4.trans.shared.b16 {%0,%1,%2,%3}, [%4];"
                 : "=r"(r[0]), "=r"(r[1]), "=r"(r[2]), "=r"(r[3]) : "r"(saddr));
}

// ============================================================================
// W -> fp16, transposed to [n][k]
// ============================================================================
__global__ __launch_bounds__(256) void wtrans_kernel(
    const float* __restrict__ Wq, const float* __restrict__ Wk,
    const float* __restrict__ Wv)
{
    __shared__ float Ts[64][65];
    const float* src = (blockIdx.y == 0) ? Wq : (blockIdx.y == 1) ? Wk : Wv;
    const int k0 = blockIdx.x * 64;
    const int tid = threadIdx.x;
#pragma unroll
    for (int s = 0; s < 16; s++) {
        int e = tid + 256 * s;
        int kk = e >> 6, n = e & 63;
        Ts[kk][n] = src[(size_t)(k0 + kk) * HD + n];
    }
    __syncthreads();
#pragma unroll
    for (int s = 0; s < 16; s++) {
        int e = tid + 256 * s;
        int n = e >> 6, kk = e & 63;
        g_wt[blockIdx.y][(size_t)n * EMB + k0 + kk] = __float2half(Ts[kk][n]);
    }
}

// ============================================================================
// Fused projection, fp16 mma m16n8k16. BM=64, 3 outs.  (unchanged from R6)
// ============================================================================
#define PSTR 36
#define PROJ_SMEM ((2*64*PSTR + 3*2*64*PSTR) * 4)

__global__ __launch_bounds__(256, 2) void proj_kernel(const float* __restrict__ x)
{
    extern __shared__ uint32_t psm[];
    uint32_t* As = psm;
    uint32_t* Bs = psm + 2 * 64 * PSTR;

    const int m0   = blockIdx.x * 64;
    const int tid  = threadIdx.x;
    const int w    = tid >> 5;
    const int lane = tid & 31;
    const int g    = lane >> 2;
    const int t    = lane & 3;
    const int wm   = w >> 2;
    const int wn   = w & 3;

    float acc[3][2][2][4];
#pragma unroll
    for (int o = 0; o < 3; o++)
#pragma unroll
        for (int i = 0; i < 2; i++)
#pragma unroll
            for (int j = 0; j < 2; j++)
#pragma unroll
                for (int q = 0; q < 4; q++) acc[o][i][j][q] = 0.f;

    float4 pa[2][2];
    uint4  pb[3], pb2[3];

    auto ldg_iter = [&](int k0c) {
#pragma unroll
        for (int s = 0; s < 2; s++) {
            int idx = tid + 256 * s;
            int r = idx >> 3, c = idx & 7;
            const float* src = &x[(size_t)(m0 + r) * EMB + k0c + c * 8];
            pa[s][0] = *(const float4*)src;
            pa[s][1] = *(const float4*)(src + 4);
        }
#pragma unroll
        for (int o = 0; o < 3; o++) {
            int r = tid >> 3, c = tid & 7;
            pb[o] = *(const uint4*)&g_wt[o][(size_t)r * EMB + k0c + c * 8];
            int idx2 = tid + 256;
            int r2 = idx2 >> 3, c2 = idx2 & 7;
            pb2[o] = *(const uint4*)&g_wt[o][(size_t)r2 * EMB + k0c + c2 * 8];
        }
    };

    auto sts_iter = [&](int buf) {
#pragma unroll
        for (int s = 0; s < 2; s++) {
            int idx = tid + 256 * s;
            int r = idx >> 3, c = idx & 7;
            uint4 v;
            v.x = pack_h2(pa[s][0].x, pa[s][0].y);
            v.y = pack_h2(pa[s][0].z, pa[s][0].w);
            v.z = pack_h2(pa[s][1].x, pa[s][1].y);
            v.w = pack_h2(pa[s][1].z, pa[s][1].w);
            *(uint4*)&As[buf * 64 * PSTR + r * PSTR + c * 4] = v;
        }
#pragma unroll
        for (int o = 0; o < 3; o++) {
            {
                int r = tid >> 3, c = tid & 7;
                *(uint4*)&Bs[(o * 2 + buf) * 64 * PSTR + r * PSTR + c * 4] = pb[o];
            }
            {
                int idx = tid + 256;
                int r = idx >> 3, c = idx & 7;
                *(uint4*)&Bs[(o * 2 + buf) * 64 * PSTR + r * PSTR + c * 4] = pb2[o];
            }
        }
    };

    ldg_iter(0);

    for (int it = 0; it < 16; it++) {
        const int buf = it & 1;
        sts_iter(buf);
        __syncthreads();
        if (it + 1 < 16) ldg_iter((it + 1) * 64);

        const uint32_t* Ab = As + buf * 64 * PSTR;
#pragma unroll
        for (int ks = 0; ks < 4; ks++) {
            uint32_t a[2][4];
#pragma unroll
            for (int am = 0; am < 2; am++) {
                int rb = wm * 32 + am * 16;
                a[am][0] = Ab[(rb + g) * PSTR + ks * 8 + t];
                a[am][1] = Ab[(rb + g + 8) * PSTR + ks * 8 + t];
                a[am][2] = Ab[(rb + g) * PSTR + ks * 8 + t + 4];
                a[am][3] = Ab[(rb + g + 8) * PSTR + ks * 8 + t + 4];
            }
#pragma unroll
            for (int o = 0; o < 3; o++) {
                const uint32_t* Bb = Bs + (o * 2 + buf) * 64 * PSTR;
#pragma unroll
                for (int bn = 0; bn < 2; bn++) {
                    int nb = wn * 16 + bn * 8;
                    uint32_t b0 = Bb[(nb + g) * PSTR + ks * 8 + t];
                    uint32_t b1 = Bb[(nb + g) * PSTR + ks * 8 + t + 4];
#pragma unroll
                    for (int am = 0; am < 2; am++)
                        mma_f16(acc[o][am][bn], a[am][0], a[am][1], a[am][2], a[am][3], b0, b1);
                }
            }
        }
        __syncthreads();
    }

    __half* outs[3] = {g_q, g_k, g_v};
#pragma unroll
    for (int o = 0; o < 3; o++)
#pragma unroll
        for (int am = 0; am < 2; am++)
#pragma unroll
            for (int bn = 0; bn < 2; bn++) {
                int r0 = m0 + wm * 32 + am * 16 + g;
                int c  = wn * 16 + bn * 8 + 2 * t;
                *(__half2*)&outs[o][(size_t)r0 * HD + c] =
                    __floats2half2_rn(acc[o][am][bn][0], acc[o][am][bn][1]);
                *(__half2*)&outs[o][(size_t)(r0 + 8) * HD + c] =
                    __floats2half2_rn(acc[o][am][bn][2], acc[o][am][bn][3]);
            }
}

// ============================================================================
// Flash attention, fp16 mma, BQ=128 (256 thr / 8 warps), kv-split x2.
// grid = 256: qt (16, heavy-first) x batch (8) x half (2).
// Warp-level causal tile skip; exp-clamp for fully-masked rows.
// ============================================================================
#define QSTR 36   // half2-words per row

__global__ __launch_bounds__(256) void attn_kernel()
{
    __shared__ uint32_t Qs[128 * QSTR];
    __shared__ uint32_t Ks[64 * QSTR];
    __shared__ uint32_t Vs[64 * QSTR];

    const int bx   = blockIdx.x;
    const int qt   = 15 - (bx >> 4);       // heavy-first (128-row tiles)
    const int sub  = bx & 15;
    const int b    = sub >> 1;
    const int half = sub & 1;
    const int q0   = qt * 128;

    const int nk     = 2 * qt + 2;         // 64-col kv tiles
    const int nhalf  = qt + 1;
    const int kt_beg = half ? nhalf : 0;
    const int kt_end = half ? nk : nhalf;

    const __half* Qg = g_q + (size_t)b * SEQ * HD;
    const __half* Kg = g_k + (size_t)b * SEQ * HD;
    const __half* Vg = g_v + (size_t)b * SEQ * HD;

    const int tid  = threadIdx.x;
    const int lane = tid & 31;
    const int w    = tid >> 5;
    const int g    = lane >> 2;
    const int t    = lane & 3;
    const int qb   = w * 16;               // warp row base within 128-tile

    // stage Q: 128 rows x 8 units = 1024 units, 4/thread
#pragma unroll
    for (int s = 0; s < 4; s++) {
        int idx = tid + 256 * s;
        int r = idx >> 3, c = idx & 7;
        *(uint4*)&Qs[r * QSTR + c * 4] = *(const uint4*)&Qg[(size_t)(q0 + r) * HD + c * 8];
    }
    __syncthreads();

    uint32_t aQ[4][4];
#pragma unroll
    for (int ks = 0; ks < 4; ks++) {
        aQ[ks][0] = Qs[(qb + g) * QSTR + ks * 8 + t];
        aQ[ks][1] = Qs[(qb + g + 8) * QSTR + ks * 8 + t];
        aQ[ks][2] = Qs[(qb + g) * QSTR + ks * 8 + t + 4];
        aQ[ks][3] = Qs[(qb + g + 8) * QSTR + ks * 8 + t + 4];
    }

    float o_[8][4];
    float m0v = -1e30f, m1v = -1e30f, l0 = 0.f, l1 = 0.f;
#pragma unroll
    for (int bn = 0; bn < 8; bn++)
#pragma unroll
        for (int q = 0; q < 4; q++) o_[bn][q] = 0.f;

    const float inv_hs = 1.f / 64.f;
    const uint32_t Vs_u = (uint32_t)__cvta_generic_to_shared(Vs);
    const uint32_t vrow_off = ((lane & 15) * QSTR + (lane >> 4) * 4) * 4;

    for (int kt = kt_beg; kt < kt_end; kt++) {
        const int k0 = kt * 64;
        __syncthreads();
        // stage K, V: 512 units each, 2/thread
#pragma unroll
        for (int s = 0; s < 2; s++) {
            int idx = tid + 256 * s;
            int r = idx >> 3, c = idx & 7;
            *(uint4*)&Ks[r * QSTR + c * 4] = *(const uint4*)&Kg[(size_t)(k0 + r) * HD + c * 8];
            *(uint4*)&Vs[r * QSTR + c * 4] = *(const uint4*)&Vg[(size_t)(k0 + r) * HD + c * 8];
        }
        __syncthreads();

        // causal tile skip: warp's rows all < k0 -> tile fully masked
        if (k0 > q0 + qb + 15) continue;

        // S = Q @ K^T
        float sa[8][4];
#pragma unroll
        for (int bn = 0; bn < 8; bn++)
#pragma unroll
            for (int q = 0; q < 4; q++) sa[bn][q] = 0.f;
#pragma unroll
        for (int ks = 0; ks < 4; ks++) {
#pragma unroll
            for (int bn = 0; bn < 8; bn++) {
                uint32_t b0 = Ks[(bn * 8 + g) * QSTR + ks * 8 + t];
                uint32_t b1 = Ks[(bn * 8 + g) * QSTR + ks * 8 + t + 4];
                mma_f16(sa[bn], aQ[ks][0], aQ[ks][1], aQ[ks][2], aQ[ks][3], b0, b1);
            }
        }

        const bool diag = (k0 + 63 > q0 + qb);   // tile touches this warp's diagonal
#pragma unroll
        for (int bn = 0; bn < 8; bn++)
#pragma unroll
            for (int q = 0; q < 4; q++) {
                float v = sa[bn][q] * inv_hs;
                if (diag) {
                    int col = k0 + bn * 8 + 2 * t + (q & 1);
                    int row = q0 + qb + g + ((q >= 2) ? 8 : 0);
                    if (col > row) v = -1e30f;
                }
                sa[bn][q] = v;
            }

        float mt0 = -1e30f, mt1 = -1e30f;
#pragma unroll
        for (int bn = 0; bn < 8; bn++) {
            mt0 = fmaxf(mt0, fmaxf(sa[bn][0], sa[bn][1]));
            mt1 = fmaxf(mt1, fmaxf(sa[bn][2], sa[bn][3]));
        }
#pragma unroll
        for (int off = 1; off <= 2; off <<= 1) {
            mt0 = fmaxf(mt0, __shfl_xor_sync(0xffffffffu, mt0, off));
            mt1 = fmaxf(mt1, __shfl_xor_sync(0xffffffffu, mt1, off));
        }
        float mn0 = fmaxf(m0v, mt0), mn1 = fmaxf(m1v, mt1);
        float c0 = __expf(m0v - mn0), c1 = __expf(m1v - mn1);
        // clamp so fully-masked rows yield p=0 (not exp(0)=1)
        float mc0 = fmaxf(mn0, -1e20f), mc1 = fmaxf(mn1, -1e20f);

        uint32_t pA[4][4];
        float lt0 = 0.f, lt1 = 0.f;
#pragma unroll
        for (int bn = 0; bn < 8; bn++) {
            float p0 = __expf(sa[bn][0] - mc0);
            float p1 = __expf(sa[bn][1] - mc0);
            float p2 = __expf(sa[bn][2] - mc1);
            float p3 = __expf(sa[bn][3] - mc1);
            lt0 += p0 + p1;  lt1 += p2 + p3;
            int ks = bn >> 1;
            if ((bn & 1) == 0) {
                pA[ks][0] = pack_h2(p0, p1);
                pA[ks][1] = pack_h2(p2, p3);
            } else {
                pA[ks][2] = pack_h2(p0, p1);
                pA[ks][3] = pack_h2(p2, p3);
            }
            o_[bn][0] *= c0; o_[bn][1] *= c0; o_[bn][2] *= c1; o_[bn][3] *= c1;
        }
#pragma unroll
        for (int off = 1; off <= 2; off <<= 1) {
            lt0 += __shfl_xor_sync(0xffffffffu, lt0, off);
            lt1 += __shfl_xor_sync(0xffffffffu, lt1, off);
        }
        l0 = l0 * c0 + lt0;  l1 = l1 * c1 + lt1;
        m0v = mn0;  m1v = mn1;

        // O += P @ V
#pragma unroll
        for (int ks = 0; ks < 4; ks++) {
#pragma unroll
            for (int bnp = 0; bnp < 4; bnp++) {
                uint32_t vb[4];
                ldmatrix_x4_t(vb, Vs_u + (ks * 16 * QSTR + bnp * 8) * 4 + vrow_off);
                mma_f16(o_[2 * bnp],     pA[ks][0], pA[ks][1], pA[ks][2], pA[ks][3], vb[0], vb[1]);
                mma_f16(o_[2 * bnp + 1], pA[ks][0], pA[ks][1], pA[ks][2], pA[ks][3], vb[2], vb[3]);
            }
        }
    }

    const int r0g = b * SEQ + q0 + qb + g;
    if (t == 0) {
        g_pm[half][r0g]     = m0v;  g_pl[half][r0g]     = l0;
        g_pm[half][r0g + 8] = m1v;  g_pl[half][r0g + 8] = l1;
    }
#pragma unroll
    for (int bn = 0; bn < 8; bn++) {
        int c = bn * 8 + 2 * t;
        *(float2*)&g_po[half][(size_t)r0g * HD + c] = make_float2(o_[bn][0], o_[bn][1]);
        *(float2*)&g_po[half][(size_t)(r0g + 8) * HD + c] = make_float2(o_[bn][2], o_[bn][3]);
    }
}

// ============================================================================
// Merge: 8 threads per row, 2x float4 per half per thread (ILP)
// ============================================================================
__global__ __launch_bounds__(256) void merge_kernel(float* __restrict__ out)
{
    int gid = blockIdx.x * 256 + threadIdx.x;   // NROWS*8
    int row = gid >> 3;
    int c   = (gid & 7) * 8;
    float m0 = g_pm[0][row], m1 = g_pm[1][row];
    float l0 = g_pl[0][row], l1 = g_pl[1][row];
    float M  = fmaxf(m0, m1);
    float w0 = __expf(m0 - M), w1 = __expf(m1 - M);
    float inv = 1.f / (l0 * w0 + l1 * w1);
    const float* p0 = &g_po[0][(size_t)row * HD + c];
    const float* p1 = &g_po[1][(size_t)row * HD + c];
    float4 a0 = *(const float4*)p0;
    float4 a1 = *(const float4*)(p0 + 4);
    float4 b0 = *(const float4*)p1;
    float4 b1 = *(const float4*)(p1 + 4);
    float4 r0, r1;
    r0.x = (a0.x * w0 + b0.x * w1) * inv;
    r0.y = (a0.y * w0 + b0.y * w1) * inv;
    r0.z = (a0.z * w0 + b0.z * w1) * inv;
    r0.w = (a0.w * w0 + b0.w * w1) * inv;
    r1.x = (a1.x * w0 + b1.x * w1) * inv;
    r1.y = (a1.y * w0 + b1.y * w1) * inv;
    r1.z = (a1.z * w0 + b1.z * w1) * inv;
    r1.w = (a1.w * w0 + b1.w * w1) * inv;
    float* dst = &out[(size_t)row * HD + c];
    *(float4*)dst = r0;
    *(float4*)(dst + 4) = r1;
}

// ============================================================================
extern "C" void kernel_launch(void* const* d_in, const int* in_sizes, int n_in,
                              void* d_out, int out_size)
{
    const float* x  = (const float*)d_in[0];
    const float* Wq = (const float*)d_in[1];
    const float* Wk = (const float*)d_in[2];
    const float* Wv = (const float*)d_in[3];
    float* out = (float*)d_out;

    wtrans_kernel<<<dim3(16, 3), 256>>>(Wq, Wk, Wv);

    cudaFuncSetAttribute(proj_kernel, cudaFuncAttributeMaxDynamicSharedMemorySize,
                         PROJ_SMEM);
    proj_kernel<<<NROWS / 64, 256, PROJ_SMEM>>>(x);

    attn_kernel<<<256, 256>>>();

    merge_kernel<<<NROWS * 8 / 256, 256>>>(out);
}